// round 3
// baseline (speedup 1.0000x reference)
#include <cuda_runtime.h>
#include <math.h>

#define HID 96
#define HC  576
#define NH  6

typedef unsigned long long ull;

// ---------------- f32x2 packed helpers ----------------
__device__ __forceinline__ ull fma2(ull a, ull b, ull c) {
    ull d;
    asm("fma.rn.f32x2 %0, %1, %2, %3;" : "=l"(d) : "l"(a), "l"(b), "l"(c));
    return d;
}
__device__ __forceinline__ ull pack2(float x, float y) {
    ull r;
    asm("mov.b64 %0, {%1, %2};" : "=l"(r) : "f"(x), "f"(y));
    return r;
}
__device__ __forceinline__ ull dup2(float x) { return pack2(x, x); }
__device__ __forceinline__ float2 unpack2(ull v) {
    float2 r;
    asm("mov.b64 {%0, %1}, %2;" : "=f"(r.x), "=f"(r.y) : "l"(v));
    return r;
}

// ---------------- scratch (device globals; no allocations allowed) ----------------
__device__ float    g_x[20000 * HID];
__device__ float    g_eemb[200000 * HID];
__device__ float    g_xl[20000 * HC];
__device__ float    g_xr[20000 * HC];
__device__ float    g_logits[200000 * NH];
__device__ unsigned g_umax[20000 * NH];
__device__ float    g_den[20000 * NH];
__device__ float    g_hmean[20000 * HID];

__device__ __forceinline__ float warpsum32(float v) {
#pragma unroll
    for (int m = 16; m; m >>= 1) v += __shfl_xor_sync(0xffffffffu, v, m);
    return v;
}
__device__ __forceinline__ float gsum16(float v) {
#pragma unroll
    for (int m = 8; m; m >>= 1) v += __shfl_xor_sync(0xffffffffu, v, m);
    return v;
}

// ---------------- encoder: out = relu(LN(in @ W + b)) ----------------
__global__ void encoder_kernel(const float* __restrict__ in, int Fin,
                               const float* __restrict__ W, const float* __restrict__ b,
                               const float* __restrict__ g, const float* __restrict__ beta,
                               float* __restrict__ out, int M)
{
    int w    = (blockIdx.x * blockDim.x + threadIdx.x) >> 5;
    int lane = threadIdx.x & 31;
    if (w >= M) return;
    float xin[4];
#pragma unroll
    for (int k = 0; k < 4; k++) xin[k] = (k < Fin) ? in[(size_t)w * Fin + k] : 0.f;
    float v[3];
#pragma unroll
    for (int j = 0; j < 3; j++) {
        int c = lane + 32 * j;
        float acc = b[c];
        for (int k = 0; k < Fin; k++) acc = fmaf(xin[k], W[k * HID + c], acc);
        v[j] = acc;
    }
    float mu = warpsum32(v[0] + v[1] + v[2]) * (1.f / 96.f);
    float q = 0.f;
#pragma unroll
    for (int j = 0; j < 3; j++) { float d = v[j] - mu; q = fmaf(d, d, q); }
    float rstd = rsqrtf(warpsum32(q) * (1.f / 96.f) + 1e-5f);
#pragma unroll
    for (int j = 0; j < 3; j++) {
        int c = lane + 32 * j;
        float y = (v[j] - mu) * rstd * g[c] + beta[c];
        out[(size_t)w * HID + c] = fmaxf(y, 0.f);
    }
}

// ---------------- GEMM: C[M,576] = A[M,96] @ B[96,576] ----------------
// 128 threads, tile 128x64, 8x8 per thread, whole K (96) staged in smem once.
// FUSED=true fuses GATv2 logit partials instead of storing C.
#define BM 128
#define BN 64
#define PAD_AS 132
#define GEMM_SMEM ((96 * PAD_AS + 96 * BN) * 4)

template<bool FUSED>
__global__ __launch_bounds__(128) void gemm96_kernel(
    const float* __restrict__ A, const float* __restrict__ B,
    const float* __restrict__ bias, float* __restrict__ C, int M,
    const int* __restrict__ src, const int* __restrict__ dst,
    const float* __restrict__ xl, const float* __restrict__ xr,
    const float* __restrict__ attw, float* __restrict__ logits)
{
    extern __shared__ float sh[];
    float* As = sh;                 // [96][PAD_AS] transposed (k-major)
    float* Bs = sh + 96 * PAD_AS;   // [96][64]

    int tid = threadIdx.x;
    int m0 = blockIdx.x * BM, n0 = blockIdx.y * BN;
    int tm = tid >> 3, tn = tid & 7;

    // load A tile (transposed). lanes (tid&7) cover 128B contiguous per row chunk.
#pragma unroll
    for (int rr = 0; rr < 8; rr++) {
        int row = (tid >> 3) + 16 * rr;
        int m = m0 + row;
#pragma unroll
        for (int kk = 0; kk < 3; kk++) {
            int kq = (tid & 7) * 4 + 32 * kk;
            float4 av = make_float4(0.f, 0.f, 0.f, 0.f);
            if (m < M) av = *(const float4*)(A + (size_t)m * 96 + kq);
            As[(kq + 0) * PAD_AS + row] = av.x;
            As[(kq + 1) * PAD_AS + row] = av.y;
            As[(kq + 2) * PAD_AS + row] = av.z;
            As[(kq + 3) * PAD_AS + row] = av.w;
        }
    }
    // load B tile: 96 rows x 64 cols
#pragma unroll
    for (int i = 0; i < 12; i++) {
        int lin = tid + 128 * i;        // 0..1535 over (96 rows x 16 float4)
        int kr = lin >> 4, nq = (lin & 15) * 4;
        *(float4*)(Bs + kr * BN + nq) = *(const float4*)(B + (size_t)kr * HC + n0 + nq);
    }
    __syncthreads();

    ull acc2[4][8];
#pragma unroll
    for (int p = 0; p < 4; p++)
#pragma unroll
        for (int j = 0; j < 8; j++) acc2[p][j] = 0ull;

#pragma unroll 4
    for (int k = 0; k < 96; k++) {
        const float* ak = As + k * PAD_AS + tm * 8;
        ulonglong2 a01 = *(const ulonglong2*)ak;
        ulonglong2 a23 = *(const ulonglong2*)(ak + 4);
        float4 b0 = *(const float4*)(Bs + k * BN + tn * 8);
        float4 b1 = *(const float4*)(Bs + k * BN + tn * 8 + 4);
        ull ap[4] = {a01.x, a01.y, a23.x, a23.y};
        ull bd[8] = {dup2(b0.x), dup2(b0.y), dup2(b0.z), dup2(b0.w),
                     dup2(b1.x), dup2(b1.y), dup2(b1.z), dup2(b1.w)};
#pragma unroll
        for (int p = 0; p < 4; p++)
#pragma unroll
            for (int j = 0; j < 8; j++)
                acc2[p][j] = fma2(ap[p], bd[j], acc2[p][j]);
    }

    float accf[8][8];
#pragma unroll
    for (int p = 0; p < 4; p++)
#pragma unroll
        for (int j = 0; j < 8; j++) {
            float2 u = unpack2(acc2[p][j]);
            accf[2 * p][j]     = u.x;
            accf[2 * p + 1][j] = u.y;
        }

    if (!FUSED) {
        float4 bq0 = make_float4(0.f, 0.f, 0.f, 0.f), bq1 = bq0;
        if (bias) {
            bq0 = *(const float4*)(bias + n0 + tn * 8);
            bq1 = *(const float4*)(bias + n0 + tn * 8 + 4);
        }
#pragma unroll
        for (int r = 0; r < 8; r++) {
            int m = m0 + tm * 8 + r;
            if (m < M) {
                float4 o0 = make_float4(accf[r][0] + bq0.x, accf[r][1] + bq0.y,
                                        accf[r][2] + bq0.z, accf[r][3] + bq0.w);
                float4 o1 = make_float4(accf[r][4] + bq1.x, accf[r][5] + bq1.y,
                                        accf[r][6] + bq1.z, accf[r][7] + bq1.w);
                float* cp = C + (size_t)m * HC + n0 + tn * 8;
                *(float4*)cp = o0;
                *(float4*)(cp + 4) = o1;
            }
        }
    } else {
        int cb = n0 + tn * 8;
        int h = cb / 96;                 // 8-col group never straddles a head
        float4 aw0 = *(const float4*)(attw + cb);
        float4 aw1 = *(const float4*)(attw + cb + 4);
        bool leader = (tn == 0) || ((n0 + (tn - 1) * 8) / 96 != h);
#pragma unroll
        for (int r = 0; r < 8; r++) {
            int m = m0 + tm * 8 + r;
            float partial = 0.f;
            if (m < M) {
                int s = src[m], d = dst[m];
                const float* xls = xl + (size_t)s * HC + cb;
                const float* xrd = xr + (size_t)d * HC + cb;
                float4 xl0 = *(const float4*)xls, xl1 = *(const float4*)(xls + 4);
                float4 xr0 = *(const float4*)xrd, xr1 = *(const float4*)(xrd + 4);
                float t;
                t = accf[r][0] + xl0.x + xr0.x; t = (t > 0.f) ? t : 0.2f * t; partial = fmaf(t, aw0.x, partial);
                t = accf[r][1] + xl0.y + xr0.y; t = (t > 0.f) ? t : 0.2f * t; partial = fmaf(t, aw0.y, partial);
                t = accf[r][2] + xl0.z + xr0.z; t = (t > 0.f) ? t : 0.2f * t; partial = fmaf(t, aw0.z, partial);
                t = accf[r][3] + xl0.w + xr0.w; t = (t > 0.f) ? t : 0.2f * t; partial = fmaf(t, aw0.w, partial);
                t = accf[r][4] + xl1.x + xr1.x; t = (t > 0.f) ? t : 0.2f * t; partial = fmaf(t, aw1.x, partial);
                t = accf[r][5] + xl1.y + xr1.y; t = (t > 0.f) ? t : 0.2f * t; partial = fmaf(t, aw1.y, partial);
                t = accf[r][6] + xl1.z + xr1.z; t = (t > 0.f) ? t : 0.2f * t; partial = fmaf(t, aw1.z, partial);
                t = accf[r][7] + xl1.w + xr1.w; t = (t > 0.f) ? t : 0.2f * t; partial = fmaf(t, aw1.w, partial);
            }
            // segmented reduce over the 8-lane tn group
#pragma unroll
            for (int off = 1; off < 8; off <<= 1) {
                float ov = __shfl_down_sync(0xffffffffu, partial, off, 8);
                int nh = (n0 + (tn + off) * 8) / 96;
                if (tn + off < 8 && nh == h) partial += ov;
            }
            if (leader && m < M)
                atomicAdd(&logits[(size_t)m * NH + h], partial);
        }
    }
}

// ---------------- segment max over logits ----------------
__global__ void segmax_kernel(const int* __restrict__ dst, const float* __restrict__ logits,
                              unsigned* __restrict__ umax, int E)
{
    int t = blockIdx.x * blockDim.x + threadIdx.x;
    if (t >= E * NH) return;
    int e = t / NH, h = t - e * NH;
    float p = logits[t];
    unsigned u = __float_as_uint(p);
    u ^= (u >> 31) ? 0xFFFFFFFFu : 0x80000000u;
    atomicMax(&umax[dst[e] * NH + h], u);
}

// ---------------- exp + denominator ----------------
__global__ void expsum_kernel(const int* __restrict__ dst, float* __restrict__ logits,
                              const unsigned* __restrict__ umax, float* __restrict__ den, int E)
{
    int t = blockIdx.x * blockDim.x + threadIdx.x;
    if (t >= E * NH) return;
    int e = t / NH, h = t - e * NH;
    int d = dst[e];
    unsigned u = umax[d * NH + h];
    float m = (u & 0x80000000u) ? __uint_as_float(u ^ 0x80000000u) : __uint_as_float(~u);
    float ex = expf(logits[t] - m);
    logits[t] = ex;
    atomicAdd(&den[d * NH + h], ex);
}

// ---------------- aggregate ----------------
__global__ void agg_kernel(const int* __restrict__ src, const int* __restrict__ dst,
                           const float* __restrict__ ex, const float* __restrict__ den,
                           const float* __restrict__ xl, float* __restrict__ hmean, int E)
{
    int e    = (blockIdx.x * blockDim.x + threadIdx.x) >> 5;
    int lane = threadIdx.x & 31;
    if (e >= E) return;
    int s = src[e], d = dst[e];
    float a = 0.f;
    if (lane < NH) a = ex[e * NH + lane] / (den[d * NH + lane] + 1e-16f);
    float alpha[NH];
#pragma unroll
    for (int h = 0; h < NH; h++) alpha[h] = __shfl_sync(0xffffffffu, a, h);
    const float* xls = xl + (size_t)s * HC;
#pragma unroll
    for (int j = 0; j < 3; j++) {
        int c = lane + 32 * j;
        float v = 0.f;
#pragma unroll
        for (int h = 0; h < NH; h++) v = fmaf(alpha[h], xls[h * 96 + c], v);
        atomicAdd(&hmean[(size_t)d * HID + c], v * (1.f / 6.f));
    }
}

// ---------------- node update ----------------
__global__ void nodeupd_kernel(const float* __restrict__ cb, const float* __restrict__ g,
                               const float* __restrict__ bt, int doElu,
                               const float* __restrict__ hmean, float* __restrict__ x, int M)
{
    int n    = (blockIdx.x * blockDim.x + threadIdx.x) >> 5;
    int lane = threadIdx.x & 31;
    if (n >= M) return;
    float v[3];
#pragma unroll
    for (int j = 0; j < 3; j++) {
        int c = lane + 32 * j;
        float hv = hmean[(size_t)n * HID + c] + cb[c];
        if (doElu) hv = (hv > 0.f) ? hv : (expf(hv) - 1.f);
        v[j] = hv;
    }
    float mu = warpsum32(v[0] + v[1] + v[2]) * (1.f / 96.f);
    float q = 0.f;
#pragma unroll
    for (int j = 0; j < 3; j++) { float d = v[j] - mu; q = fmaf(d, d, q); }
    float rstd = rsqrtf(warpsum32(q) * (1.f / 96.f) + 1e-5f);
#pragma unroll
    for (int j = 0; j < 3; j++) {
        int c = lane + 32 * j;
        float y = (v[j] - mu) * rstd * g[c] + bt[c];
        x[(size_t)n * HID + c] += y;
    }
}

// ---------------- fused predictor MLP ----------------
#define S_P1W 36864
#define S_P2W 8192
#define S_P3W 64
#define S_C1  384
#define S_C2  192
#define S_CTX 9216
#define PRED_SMEM ((S_P1W + S_P2W + S_P3W + S_C1 + S_C2 + S_CTX) * 4)

__global__ __launch_bounds__(256) void predictor_kernel(
    const int* __restrict__ src, const int* __restrict__ dst,
    const float* __restrict__ xnode, const float* __restrict__ eemb,
    const float* __restrict__ p1w, const float* __restrict__ p1b,
    const float* __restrict__ p1g, const float* __restrict__ p1bt,
    const float* __restrict__ p2w, const float* __restrict__ p2b,
    const float* __restrict__ p2g, const float* __restrict__ p2bt,
    const float* __restrict__ p3w, const float* __restrict__ p3b,
    float* __restrict__ out, int E)
{
    extern __shared__ float sm[];
    float* s_p1w = sm;
    float* s_p2w = s_p1w + S_P1W;
    float* s_p3w = s_p2w + S_P2W;
    float* s_c1  = s_p3w + S_P3W;
    float* s_c2  = s_c1 + S_C1;
    float* s_ctx = s_c2 + S_C2;

    int tid = threadIdx.x;
    for (int i = tid; i < S_P1W / 4; i += 256) ((float4*)s_p1w)[i] = ((const float4*)p1w)[i];
    for (int i = tid; i < S_P2W / 4; i += 256) ((float4*)s_p2w)[i] = ((const float4*)p2w)[i];
    if (tid < 64) s_p3w[tid] = p3w[tid];
    if (tid < 128) { s_c1[tid] = p1b[tid]; s_c1[128 + tid] = p1g[tid]; s_c1[256 + tid] = p1bt[tid]; }
    if (tid < 64)  { s_c2[tid] = p2b[tid]; s_c2[64 + tid]  = p2g[tid]; s_c2[128 + tid] = p2bt[tid]; }

    int eb = blockIdx.x * 32;
    for (int i = tid; i < 32 * 288; i += 256) {
        int el = i / 288, k = i - el * 288;
        int e = eb + el; if (e > E - 1) e = E - 1;
        float v;
        if (k < 96)       v = xnode[(size_t)src[e] * HID + k];
        else if (k < 192) v = xnode[(size_t)dst[e] * HID + (k - 96)];
        else              v = eemb[(size_t)e * HID + (k - 192)];
        s_ctx[el * 288 + k] = v;
    }
    __syncthreads();

    int p = tid >> 4, jg = tid & 15;
    int el0 = 2 * p, el1 = 2 * p + 1;
    const float* c0 = s_ctx + el0 * 288;
    const float* c1 = s_ctx + el1 * 288;

    int jA = jg * 4, jB = 64 + jg * 4;
    ull H0A0 = 0, H0A1 = 0, H0B0 = 0, H0B1 = 0;
    ull H1A0 = 0, H1A1 = 0, H1B0 = 0, H1B1 = 0;
    for (int k = 0; k < 288; k++) {
        ull a0d = dup2(c0[k]), a1d = dup2(c1[k]);
        ulonglong2 wa = *(const ulonglong2*)(s_p1w + k * 128 + jA);
        ulonglong2 wb = *(const ulonglong2*)(s_p1w + k * 128 + jB);
        H0A0 = fma2(a0d, wa.x, H0A0); H0A1 = fma2(a0d, wa.y, H0A1);
        H0B0 = fma2(a0d, wb.x, H0B0); H0B1 = fma2(a0d, wb.y, H0B1);
        H1A0 = fma2(a1d, wa.x, H1A0); H1A1 = fma2(a1d, wa.y, H1A1);
        H1B0 = fma2(a1d, wb.x, H1B0); H1B1 = fma2(a1d, wb.y, H1B1);
    }
    float h0a[4], h0b[4], h1a[4], h1b[4];
    { float2 u;
      u = unpack2(H0A0); h0a[0] = u.x; h0a[1] = u.y;
      u = unpack2(H0A1); h0a[2] = u.x; h0a[3] = u.y;
      u = unpack2(H0B0); h0b[0] = u.x; h0b[1] = u.y;
      u = unpack2(H0B1); h0b[2] = u.x; h0b[3] = u.y;
      u = unpack2(H1A0); h1a[0] = u.x; h1a[1] = u.y;
      u = unpack2(H1A1); h1a[2] = u.x; h1a[3] = u.y;
      u = unpack2(H1B0); h1b[0] = u.x; h1b[1] = u.y;
      u = unpack2(H1B1); h1b[2] = u.x; h1b[3] = u.y; }
#pragma unroll
    for (int i = 0; i < 4; i++) {
        h0a[i] += s_c1[jA + i]; h0b[i] += s_c1[jB + i];
        h1a[i] += s_c1[jA + i]; h1b[i] += s_c1[jB + i];
    }
    {
        float s0 = 0, s1 = 0;
#pragma unroll
        for (int i = 0; i < 4; i++) { s0 += h0a[i] + h0b[i]; s1 += h1a[i] + h1b[i]; }
        float mu0 = gsum16(s0) * (1.f / 128.f), mu1 = gsum16(s1) * (1.f / 128.f);
        float q0 = 0, q1 = 0;
#pragma unroll
        for (int i = 0; i < 4; i++) {
            float d; d = h0a[i] - mu0; q0 = fmaf(d, d, q0); d = h0b[i] - mu0; q0 = fmaf(d, d, q0);
            d = h1a[i] - mu1; q1 = fmaf(d, d, q1); d = h1b[i] - mu1; q1 = fmaf(d, d, q1);
        }
        float r0 = rsqrtf(gsum16(q0) * (1.f / 128.f) + 1e-5f);
        float r1 = rsqrtf(gsum16(q1) * (1.f / 128.f) + 1e-5f);
#pragma unroll
        for (int i = 0; i < 4; i++) {
            h0a[i] = fmaxf((h0a[i] - mu0) * r0 * s_c1[128 + jA + i] + s_c1[256 + jA + i], 0.f);
            h0b[i] = fmaxf((h0b[i] - mu0) * r0 * s_c1[128 + jB + i] + s_c1[256 + jB + i], 0.f);
            h1a[i] = fmaxf((h1a[i] - mu1) * r1 * s_c1[128 + jA + i] + s_c1[256 + jA + i], 0.f);
            h1b[i] = fmaxf((h1b[i] - mu1) * r1 * s_c1[128 + jB + i] + s_c1[256 + jB + i], 0.f);
        }
    }
    __syncthreads();
#pragma unroll
    for (int i = 0; i < 4; i++) {
        s_ctx[el0 * 288 + jA + i] = h0a[i]; s_ctx[el0 * 288 + jB + i] = h0b[i];
        s_ctx[el1 * 288 + jA + i] = h1a[i]; s_ctx[el1 * 288 + jB + i] = h1b[i];
    }
    __syncthreads();

    int j2 = jg * 4;
    ull G00 = 0, G01 = 0, G10 = 0, G11 = 0;
    const float* hh0 = s_ctx + el0 * 288;
    const float* hh1 = s_ctx + el1 * 288;
    for (int k = 0; k < 128; k++) {
        ull a0d = dup2(hh0[k]), a1d = dup2(hh1[k]);
        ulonglong2 w = *(const ulonglong2*)(s_p2w + k * 64 + j2);
        G00 = fma2(a0d, w.x, G00); G01 = fma2(a0d, w.y, G01);
        G10 = fma2(a1d, w.x, G10); G11 = fma2(a1d, w.y, G11);
    }
    float g0[4], g1[4];
    { float2 u;
      u = unpack2(G00); g0[0] = u.x; g0[1] = u.y;
      u = unpack2(G01); g0[2] = u.x; g0[3] = u.y;
      u = unpack2(G10); g1[0] = u.x; g1[1] = u.y;
      u = unpack2(G11); g1[2] = u.x; g1[3] = u.y; }
#pragma unroll
    for (int i = 0; i < 4; i++) { g0[i] += s_c2[j2 + i]; g1[i] += s_c2[j2 + i]; }
    {
        float s0 = 0, s1 = 0;
#pragma unroll
        for (int i = 0; i < 4; i++) { s0 += g0[i]; s1 += g1[i]; }
        float mu0 = gsum16(s0) * (1.f / 64.f), mu1 = gsum16(s1) * (1.f / 64.f);
        float q0 = 0, q1 = 0;
#pragma unroll
        for (int i = 0; i < 4; i++) {
            float d; d = g0[i] - mu0; q0 = fmaf(d, d, q0);
            d = g1[i] - mu1; q1 = fmaf(d, d, q1);
        }
        float r0 = rsqrtf(gsum16(q0) * (1.f / 64.f) + 1e-5f);
        float r1 = rsqrtf(gsum16(q1) * (1.f / 64.f) + 1e-5f);
#pragma unroll
        for (int i = 0; i < 4; i++) {
            g0[i] = fmaxf((g0[i] - mu0) * r0 * s_c2[64 + j2 + i] + s_c2[128 + j2 + i], 0.f);
            g1[i] = fmaxf((g1[i] - mu1) * r1 * s_c2[64 + j2 + i] + s_c2[128 + j2 + i], 0.f);
        }
    }
    float o0 = 0, o1 = 0;
#pragma unroll
    for (int i = 0; i < 4; i++) {
        o0 = fmaf(g0[i], s_p3w[j2 + i], o0);
        o1 = fmaf(g1[i], s_p3w[j2 + i], o1);
    }
    o0 = gsum16(o0); o1 = gsum16(o1);
    if (jg == 0) {
        float pb = p3b[0];
        int e0 = eb + el0, e1 = eb + el1;
        if (e0 < E) out[e0] = o0 + pb;
        if (e1 < E) out[e1] = o1 + pb;
    }
}

// ---------------- launch ----------------
extern "C" void kernel_launch(void* const* d_in, const int* in_sizes, int n_in,
                              void* d_out, int out_size)
{
    const float* x         = (const float*)d_in[0];
    const float* edge_attr = (const float*)d_in[1];
    const int*   edge_idx  = (const int*)d_in[2];
    const float* ne_w = (const float*)d_in[3];
    const float* ne_b = (const float*)d_in[4];
    const float* ne_g = (const float*)d_in[5];
    const float* ne_bt = (const float*)d_in[6];
    const float* ee_w = (const float*)d_in[7];
    const float* ee_b = (const float*)d_in[8];
    const float* ee_g = (const float*)d_in[9];
    const float* ee_bt = (const float*)d_in[10];
    const float* Wl = (const float*)d_in[11];
    const float* bl = (const float*)d_in[12];
    const float* Wr = (const float*)d_in[13];
    const float* br = (const float*)d_in[14];
    const float* We = (const float*)d_in[15];
    const float* attw = (const float*)d_in[16];
    const float* cbias = (const float*)d_in[17];
    const float* lng = (const float*)d_in[18];
    const float* lnb = (const float*)d_in[19];
    const float* p1w = (const float*)d_in[20];
    const float* p1b = (const float*)d_in[21];
    const float* p1g = (const float*)d_in[22];
    const float* p1bt = (const float*)d_in[23];
    const float* p2w = (const float*)d_in[24];
    const float* p2b = (const float*)d_in[25];
    const float* p2g = (const float*)d_in[26];
    const float* p2bt = (const float*)d_in[27];
    const float* p3w = (const float*)d_in[28];
    const float* p3b = (const float*)d_in[29];

    int Nn = in_sizes[0] / 4;
    int E  = in_sizes[1] / 3;
    const int* srcp = edge_idx;
    const int* dstp = edge_idx + E;
    float* outp = (float*)d_out;

    void *px_, *pe_, *pxl_, *pxr_, *plog_, *pumax_, *pden_, *phm_;
    cudaGetSymbolAddress(&px_, g_x);
    cudaGetSymbolAddress(&pe_, g_eemb);
    cudaGetSymbolAddress(&pxl_, g_xl);
    cudaGetSymbolAddress(&pxr_, g_xr);
    cudaGetSymbolAddress(&plog_, g_logits);
    cudaGetSymbolAddress(&pumax_, g_umax);
    cudaGetSymbolAddress(&pden_, g_den);
    cudaGetSymbolAddress(&phm_, g_hmean);
    float* px = (float*)px_;   float* pe = (float*)pe_;
    float* pxl = (float*)pxl_; float* pxr = (float*)pxr_;
    float* plog = (float*)plog_;
    unsigned* pumax = (unsigned*)pumax_;
    float* pden = (float*)pden_; float* phm = (float*)phm_;

    cudaFuncSetAttribute(gemm96_kernel<false>,
                         cudaFuncAttributeMaxDynamicSharedMemorySize, GEMM_SMEM);
    cudaFuncSetAttribute(gemm96_kernel<true>,
                         cudaFuncAttributeMaxDynamicSharedMemorySize, GEMM_SMEM);
    cudaFuncSetAttribute(predictor_kernel,
                         cudaFuncAttributeMaxDynamicSharedMemorySize, PRED_SMEM);

    encoder_kernel<<<(Nn + 7) / 8, 256>>>(x, 4, ne_w, ne_b, ne_g, ne_bt, px, Nn);
    encoder_kernel<<<(E + 7) / 8, 256>>>(edge_attr, 3, ee_w, ee_b, ee_g, ee_bt, pe, E);

    dim3 gN((Nn + BM - 1) / BM, HC / BN);
    dim3 gE((E + BM - 1) / BM, HC / BN);

    for (int l = 0; l < 3; l++) {
        const float* Wl_l = Wl + (size_t)l * 96 * HC;
        const float* Wr_l = Wr + (size_t)l * 96 * HC;
        const float* We_l = We + (size_t)l * 96 * HC;
        gemm96_kernel<false><<<gN, 128, GEMM_SMEM>>>(px, Wl_l, bl + l * HC, pxl, Nn,
                                                     0, 0, 0, 0, 0, 0);
        gemm96_kernel<false><<<gN, 128, GEMM_SMEM>>>(px, Wr_l, br + l * HC, pxr, Nn,
                                                     0, 0, 0, 0, 0, 0);

        cudaMemsetAsync(plog, 0, (size_t)E * NH * sizeof(float), 0);
        cudaMemsetAsync(pumax, 0, (size_t)Nn * NH * sizeof(unsigned), 0);
        cudaMemsetAsync(pden, 0, (size_t)Nn * NH * sizeof(float), 0);
        cudaMemsetAsync(phm, 0, (size_t)Nn * HID * sizeof(float), 0);

        gemm96_kernel<true><<<gE, 128, GEMM_SMEM>>>(pe, We_l, (const float*)0, (float*)0, E,
                                                    srcp, dstp, pxl, pxr,
                                                    attw + l * NH * 96, plog);

        segmax_kernel<<<(E * NH + 255) / 256, 256>>>(dstp, plog, pumax, E);
        expsum_kernel<<<(E * NH + 255) / 256, 256>>>(dstp, plog, pumax, pden, E);
        agg_kernel<<<(E + 7) / 8, 256>>>(srcp, dstp, plog, pden, pxl, phm, E);
        nodeupd_kernel<<<(Nn + 7) / 8, 256>>>(cbias + l * HID, lng + l * HID,
                                              lnb + l * HID, (l < 2) ? 1 : 0, phm, px, Nn);
    }

    predictor_kernel<<<(E + 31) / 32, 256, PRED_SMEM>>>(
        srcp, dstp, px, pe,
        p1w, p1b, p1g, p1bt, p2w, p2b, p2g, p2bt, p3w, p3b, outp, E);
}